// round 2
// baseline (speedup 1.0000x reference)
#include <cuda_runtime.h>

// Problem constants
#define BB 8192
#define SS 64
#define HH 32
#define WARPS 4   // batch elements per block (1 warp each)

// Scratch for L2 input projection: [B][S][128] gate pre-activations.
// (__device__ global array: allocation-free per harness rules.)
__device__ float g_xg2[BB * SS * 128];

__device__ __forceinline__ float sigf(float x) {
    // exact saturation at extremes via inf handling
    return 1.0f / (1.0f + __expf(-x));
}
__device__ __forceinline__ float tanhf_(float x) {
    // tanh(x) = 1 - 2/(e^{2x}+1); saturates correctly for |x| large
    return 1.0f - 2.0f / (__expf(2.0f * x) + 1.0f);
}

__global__ void __launch_bounds__(WARPS * 32)
lstm_fused_kernel(const float* __restrict__ x_main,   // [B,S,4]
                  const float* __restrict__ x_sfc,    // [B,5]
                  const float* __restrict__ w_sfc1, const float* __restrict__ b_sfc1,
                  const float* __restrict__ w_sfc2, const float* __restrict__ b_sfc2,
                  const float* __restrict__ w_ih1,  const float* __restrict__ w_hh1,
                  const float* __restrict__ b_ih1,  const float* __restrict__ b_hh1,
                  const float* __restrict__ w_ih2,  const float* __restrict__ w_hh2,
                  const float* __restrict__ b_ih2,  const float* __restrict__ b_hh2,
                  const float* __restrict__ w_out,  const float* __restrict__ b_out,
                  float* __restrict__ out)           // [B,S,1]
{
    __shared__ float s_out1[WARPS][SS][HH];

    const int warp = threadIdx.x >> 5;
    const int u    = threadIdx.x & 31;
    const int b    = blockIdx.x * WARPS + warp;
    float (*my1)[HH] = s_out1[warp];

    // ---------------- h0, c0 from surface MLPs ----------------
    float h, c;
    {
        float sf[5];
#pragma unroll
        for (int k = 0; k < 5; k++) sf[k] = x_sfc[b * 5 + k];
        float a1 = b_sfc1[u];
        float a2 = b_sfc2[u];
#pragma unroll
        for (int k = 0; k < 5; k++) {
            a1 += w_sfc1[u * 5 + k] * sf[k];
            a2 += w_sfc2[u * 5 + k] * sf[k];
        }
        h = tanhf_(a1);
        c = tanhf_(a2);
    }

    // ---------------- Layer 1 (runs over time-reversed input) ----------------
    {
        float wih[4][4], whh[4][32], bias[4];
#pragma unroll
        for (int g = 0; g < 4; g++) {
            const int r = g * 32 + u;            // PyTorch gate order i,f,g,o
            bias[g] = b_ih1[r] + b_hh1[r];
#pragma unroll
            for (int k = 0; k < 4; k++)  wih[g][k] = w_ih1[r * 4 + k];
#pragma unroll
            for (int j = 0; j < 32; j++) whh[g][j] = w_hh1[r * 32 + j];
        }

        for (int t = 0; t < SS; t++) {
            const int s = SS - 1 - t;  // reversed-time input; output slot = s (flip back)
            const float4 xv =
                *reinterpret_cast<const float4*>(x_main + ((size_t)b * SS + s) * 4);

            float a0 = bias[0] + wih[0][0] * xv.x + wih[0][1] * xv.y + wih[0][2] * xv.z + wih[0][3] * xv.w;
            float a1 = bias[1] + wih[1][0] * xv.x + wih[1][1] * xv.y + wih[1][2] * xv.z + wih[1][3] * xv.w;
            float a2 = bias[2] + wih[2][0] * xv.x + wih[2][1] * xv.y + wih[2][2] * xv.z + wih[2][3] * xv.w;
            float a3 = bias[3] + wih[3][0] * xv.x + wih[3][1] * xv.y + wih[3][2] * xv.z + wih[3][3] * xv.w;

#pragma unroll
            for (int j = 0; j < 32; j++) {
                const float hj = __shfl_sync(0xffffffffu, h, j);
                a0 += whh[0][j] * hj;
                a1 += whh[1][j] * hj;
                a2 += whh[2][j] * hj;
                a3 += whh[3][j] * hj;
            }

            const float ig = sigf(a0);
            const float fg = sigf(a1);
            const float gg = tanhf_(a2);
            const float og = sigf(a3);
            c = fg * c + ig * gg;
            h = og * tanhf_(c);
            my1[s][u] = h;
        }
    }
    __syncwarp();

    // ---------------- L2 input projection (time-parallel) -> scratch ----------------
    {
        float wih2[4][32], bias[4];
#pragma unroll
        for (int g = 0; g < 4; g++) {
            const int r = g * 32 + u;
            bias[g] = b_ih2[r] + b_hh2[r];
#pragma unroll
            for (int j = 0; j < 32; j++) wih2[g][j] = w_ih2[r * 32 + j];
        }
        float* __restrict__ dst = g_xg2 + (size_t)b * SS * 128;

        for (int t = 0; t < SS; t++) {
            float a0 = bias[0], a1 = bias[1], a2 = bias[2], a3 = bias[3];
#pragma unroll
            for (int j = 0; j < 32; j++) {
                const float xj = my1[t][j];   // LDS broadcast (all lanes same addr)
                a0 += wih2[0][j] * xj;
                a1 += wih2[1][j] * xj;
                a2 += wih2[2][j] * xj;
                a3 += wih2[3][j] * xj;
            }
            dst[t * 128 +       u] = a0;   // coalesced per gate group
            dst[t * 128 +  32 + u] = a1;
            dst[t * 128 +  64 + u] = a2;
            dst[t * 128 +  96 + u] = a3;
        }
    }

    // ---------------- Layer 2 recurrence + output projection ----------------
    {
        float whh2[4][32];
#pragma unroll
        for (int g = 0; g < 4; g++) {
            const int r = g * 32 + u;
#pragma unroll
            for (int j = 0; j < 32; j++) whh2[g][j] = w_hh2[r * 32 + j];
        }
        const float wo = w_out[u];
        const float bo = b_out[0];
        const float* __restrict__ src = g_xg2 + (size_t)b * SS * 128;

        float h2 = 0.0f, c2 = 0.0f;
        for (int t = 0; t < SS; t++) {
            // issue loads first; they are consumed only after the matvec chain starts
            float a0 = src[t * 128 +       u];
            float a1 = src[t * 128 +  32 + u];
            float a2 = src[t * 128 +  64 + u];
            float a3 = src[t * 128 +  96 + u];

#pragma unroll
            for (int j = 0; j < 32; j++) {
                const float hj = __shfl_sync(0xffffffffu, h2, j);
                a0 += whh2[0][j] * hj;
                a1 += whh2[1][j] * hj;
                a2 += whh2[2][j] * hj;
                a3 += whh2[3][j] * hj;
            }

            const float ig = sigf(a0);
            const float fg = sigf(a1);
            const float gg = tanhf_(a2);
            const float og = sigf(a3);
            c2 = fg * c2 + ig * gg;
            h2 = og * tanhf_(c2);

            // y[b,t] = w_out . h2 + b_out   (NY = 1) : warp reduction
            float p = wo * h2;
#pragma unroll
            for (int off = 16; off; off >>= 1)
                p += __shfl_xor_sync(0xffffffffu, p, off);
            if (u == 0) out[(size_t)b * SS + t] = p + bo;
        }
    }
}

extern "C" void kernel_launch(void* const* d_in, const int* in_sizes, int n_in,
                              void* d_out, int out_size)
{
    const float* x_main = (const float*)d_in[0];
    const float* x_sfc  = (const float*)d_in[1];
    const float* w_sfc1 = (const float*)d_in[2];
    const float* b_sfc1 = (const float*)d_in[3];
    const float* w_sfc2 = (const float*)d_in[4];
    const float* b_sfc2 = (const float*)d_in[5];
    const float* w_ih1  = (const float*)d_in[6];
    const float* w_hh1  = (const float*)d_in[7];
    const float* b_ih1  = (const float*)d_in[8];
    const float* b_hh1  = (const float*)d_in[9];
    const float* w_ih2  = (const float*)d_in[10];
    const float* w_hh2  = (const float*)d_in[11];
    const float* b_ih2  = (const float*)d_in[12];
    const float* b_hh2  = (const float*)d_in[13];
    const float* w_out  = (const float*)d_in[14];
    const float* b_out  = (const float*)d_in[15];
    float* out = (float*)d_out;

    dim3 grid(BB / WARPS);   // 2048 blocks
    dim3 block(WARPS * 32);  // 128 threads
    lstm_fused_kernel<<<grid, block>>>(x_main, x_sfc,
                                       w_sfc1, b_sfc1, w_sfc2, b_sfc2,
                                       w_ih1, w_hh1, b_ih1, b_hh1,
                                       w_ih2, w_hh2, b_ih2, b_hh2,
                                       w_out, b_out, out);
}

// round 6
// speedup vs baseline: 1.6236x; 1.6236x over previous
#include <cuda_runtime.h>

#define BB 8192
#define SS 64

typedef unsigned long long ull;

// L2 input-projection scratch: [B][S][64] packed pairs ((i,f) x32, (g,o) x32). 256 MB.
__device__ ull g_xg2[(size_t)BB * SS * 64];

__device__ __forceinline__ ull ffma2(ull a, ull b, ull c) {
    ull d;
    asm("fma.rn.f32x2 %0, %1, %2, %3;" : "=l"(d) : "l"(a), "l"(b), "l"(c));
    return d;
}
__device__ __forceinline__ ull pack2(float lo, float hi) {
    ull d;
    asm("mov.b64 %0, {%1, %2};" : "=l"(d) : "f"(lo), "f"(hi));
    return d;
}
__device__ __forceinline__ void unpack2(ull v, float& lo, float& hi) {
    asm("mov.b64 {%0, %1}, %2;" : "=f"(lo), "=f"(hi) : "l"(v));
}
__device__ __forceinline__ float sigf(float x)   { return 1.0f / (1.0f + __expf(-x)); }
__device__ __forceinline__ float tanhf_(float x) { return 1.0f - 2.0f / (__expf(2.0f * x) + 1.0f); }

// Load a [128][32] gate-major weight matrix, packing rows (u,32+u) -> wif and (64+u,96+u) -> wgo.
__device__ __forceinline__ void load_pack_w(const float* __restrict__ W, int u,
                                            ull* wif, ull* wgo) {
#pragma unroll
    for (int q = 0; q < 8; q++) {
        float4 vi = *reinterpret_cast<const float4*>(W + (u      ) * 32 + q * 4);
        float4 vf = *reinterpret_cast<const float4*>(W + (32 + u) * 32 + q * 4);
        float4 vg = *reinterpret_cast<const float4*>(W + (64 + u) * 32 + q * 4);
        float4 vo = *reinterpret_cast<const float4*>(W + (96 + u) * 32 + q * 4);
        wif[q * 4 + 0] = pack2(vi.x, vf.x);
        wif[q * 4 + 1] = pack2(vi.y, vf.y);
        wif[q * 4 + 2] = pack2(vi.z, vf.z);
        wif[q * 4 + 3] = pack2(vi.w, vf.w);
        wgo[q * 4 + 0] = pack2(vg.x, vo.x);
        wgo[q * 4 + 1] = pack2(vg.y, vo.y);
        wgo[q * 4 + 2] = pack2(vg.z, vo.z);
        wgo[q * 4 + 3] = pack2(vg.w, vo.w);
    }
}

// 32-term dual packed dot: aif/ago accumulate over duplicated multiplicands hp[j]=((x,x),(x,x)).
__device__ __forceinline__ void dot32(const ulonglong2* __restrict__ hp,
                                      const ull* wif, const ull* wgo,
                                      ull& aif, ull& ago) {
#pragma unroll
    for (int j = 0; j < 16; j++) {
        ulonglong2 hd = hp[j];                 // LDS.128, broadcast (all lanes same addr)
        aif = ffma2(wif[2 * j],     hd.x, aif);
        ago = ffma2(wgo[2 * j],     hd.x, ago);
        aif = ffma2(wif[2 * j + 1], hd.y, aif);
        ago = ffma2(wgo[2 * j + 1], hd.y, ago);
    }
}

__device__ __forceinline__ void lstm_update(ull aif, ull ago, float& h, float& c) {
    float ai, af, ag, ao;
    unpack2(aif, ai, af);
    unpack2(ago, ag, ao);
    const float ig = sigf(ai);
    const float fg = sigf(af);
    const float gg = tanhf_(ag);
    const float og = sigf(ao);
    c = fg * c + ig * gg;
    h = og * tanhf_(c);
}

__global__ void __launch_bounds__(32, 10)
lstm_fused_kernel(const float* __restrict__ x_main,   // [B,S,4]
                  const float* __restrict__ x_sfc,    // [B,5]
                  const float* __restrict__ w_sfc1, const float* __restrict__ b_sfc1,
                  const float* __restrict__ w_sfc2, const float* __restrict__ b_sfc2,
                  const float* __restrict__ w_ih1,  const float* __restrict__ w_hh1,
                  const float* __restrict__ b_ih1,  const float* __restrict__ b_hh1,
                  const float* __restrict__ w_ih2,  const float* __restrict__ w_hh2,
                  const float* __restrict__ b_ih2,  const float* __restrict__ b_hh2,
                  const float* __restrict__ w_out,  const float* __restrict__ b_out,
                  float* __restrict__ out)            // [B,S,1]
{
    // Rows 0..63: out1 history (duplicated pairs). Row 64: h0 / L2 state buf A. Row 65: L2 state buf B.
    __shared__ ull hist[(SS + 2) * 32];

    const int u = threadIdx.x;      // hidden unit (lane)
    const int b = blockIdx.x;       // batch element (1 warp per block)

    // ---------------- h0, c0 from surface MLPs ----------------
    float h, c;
    {
        float sf[5];
#pragma unroll
        for (int k = 0; k < 5; k++) sf[k] = x_sfc[b * 5 + k];
        float a1 = b_sfc1[u];
        float a2 = b_sfc2[u];
#pragma unroll
        for (int k = 0; k < 5; k++) {
            a1 += w_sfc1[u * 5 + k] * sf[k];
            a2 += w_sfc2[u * 5 + k] * sf[k];
        }
        h = tanhf_(a1);
        c = tanhf_(a2);
    }

    // ---------------- Phase 1: Layer-1 recurrence over time-reversed input ----------------
    {
        ull wif[32], wgo[32];
        load_pack_w(w_hh1, u, wif, wgo);

        ull xif[4], xgo[4];
        {
            float4 wi4 = *reinterpret_cast<const float4*>(w_ih1 + (u      ) * 4);
            float4 wf4 = *reinterpret_cast<const float4*>(w_ih1 + (32 + u) * 4);
            float4 wg4 = *reinterpret_cast<const float4*>(w_ih1 + (64 + u) * 4);
            float4 wo4 = *reinterpret_cast<const float4*>(w_ih1 + (96 + u) * 4);
            xif[0] = pack2(wi4.x, wf4.x); xif[1] = pack2(wi4.y, wf4.y);
            xif[2] = pack2(wi4.z, wf4.z); xif[3] = pack2(wi4.w, wf4.w);
            xgo[0] = pack2(wg4.x, wo4.x); xgo[1] = pack2(wg4.y, wo4.y);
            xgo[2] = pack2(wg4.z, wo4.z); xgo[3] = pack2(wg4.w, wo4.w);
        }
        const ull bif = pack2(b_ih1[u] + b_hh1[u],           b_ih1[32 + u] + b_hh1[32 + u]);
        const ull bgo = pack2(b_ih1[64 + u] + b_hh1[64 + u], b_ih1[96 + u] + b_hh1[96 + u]);

        hist[SS * 32 + u] = pack2(h, h);     // h_prev for first step lives in row 64
        __syncthreads();

        const float4* xb = reinterpret_cast<const float4*>(x_main + (size_t)b * SS * 4);

        for (int t = 0; t < SS; t++) {
            const int s = SS - 1 - t;        // reversed-time input; output slot s (flip back)
            const float4 xv = xb[s];

            ull aif = bif, ago = bgo;
            ull xd;
            xd = pack2(xv.x, xv.x); aif = ffma2(xif[0], xd, aif); ago = ffma2(xgo[0], xd, ago);
            xd = pack2(xv.y, xv.y); aif = ffma2(xif[1], xd, aif); ago = ffma2(xgo[1], xd, ago);
            xd = pack2(xv.z, xv.z); aif = ffma2(xif[2], xd, aif); ago = ffma2(xgo[2], xd, ago);
            xd = pack2(xv.w, xv.w); aif = ffma2(xif[3], xd, aif); ago = ffma2(xgo[3], xd, ago);

            dot32(reinterpret_cast<const ulonglong2*>(hist + (s + 1) * 32), wif, wgo, aif, ago);
            lstm_update(aif, ago, h, c);

            hist[s * 32 + u] = pack2(h, h);
            __syncthreads();                 // nw=1 BAR: ~3 cyc
        }
    }

    // ---------------- Phase 2: L2 input projection (time-parallel) -> packed scratch ----------------
    {
        ull wif[32], wgo[32];
        load_pack_w(w_ih2, u, wif, wgo);
        const ull bif = pack2(b_ih2[u] + b_hh2[u],           b_ih2[32 + u] + b_hh2[32 + u]);
        const ull bgo = pack2(b_ih2[64 + u] + b_hh2[64 + u], b_ih2[96 + u] + b_hh2[96 + u]);

        ull* __restrict__ dst = g_xg2 + (size_t)b * SS * 64;
        for (int t = 0; t < SS; t++) {
            ull aif = bif, ago = bgo;
            dot32(reinterpret_cast<const ulonglong2*>(hist + t * 32), wif, wgo, aif, ago);
            dst[t * 64 + u]      = aif;      // coalesced STG.64
            dst[t * 64 + 32 + u] = ago;
        }
    }

    // ---------------- Phase 3: L2 recurrence + output projection ----------------
    {
        ull wif[32], wgo[32];
        load_pack_w(w_hh2, u, wif, wgo);
        const float wo = w_out[u];
        const float bo = b_out[0];
        const ull* __restrict__ src = g_xg2 + (size_t)b * SS * 64;

        float h2 = 0.0f, c2 = 0.0f;
        hist[SS * 32 + u] = pack2(0.0f, 0.0f);   // state buffer A (row 64) <- zeros

        // prefetch two steps of gate pre-activations
        ull nif0 = src[u],          ngo0 = src[32 + u];
        ull nif1 = src[64 + u],     ngo1 = src[64 + 32 + u];
        __syncthreads();

        for (int t = 0; t < SS; t++) {
            ull aif = nif0, ago = ngo0;
            nif0 = nif1; ngo0 = ngo1;
            if (t + 2 < SS) {
                nif1 = src[(t + 2) * 64 + u];
                ngo1 = src[(t + 2) * 64 + 32 + u];
            }

            const int rd = SS + (t & 1);         // double-buffered state rows 64/65
            const int wr = SS + ((t & 1) ^ 1);
            dot32(reinterpret_cast<const ulonglong2*>(hist + rd * 32), wif, wgo, aif, ago);
            lstm_update(aif, ago, h2, c2);

            hist[wr * 32 + u] = pack2(h2, h2);

            // y[b,t] = w_out . h2 + b_out (NY=1): butterfly off the critical path
            float p = wo * h2;
#pragma unroll
            for (int off = 16; off; off >>= 1)
                p += __shfl_xor_sync(0xffffffffu, p, off);
            if (u == 0) out[(size_t)b * SS + t] = p + bo;

            __syncthreads();
        }
    }
}

extern "C" void kernel_launch(void* const* d_in, const int* in_sizes, int n_in,
                              void* d_out, int out_size)
{
    const float* x_main = (const float*)d_in[0];
    const float* x_sfc  = (const float*)d_in[1];
    const float* w_sfc1 = (const float*)d_in[2];
    const float* b_sfc1 = (const float*)d_in[3];
    const float* w_sfc2 = (const float*)d_in[4];
    const float* b_sfc2 = (const float*)d_in[5];
    const float* w_ih1  = (const float*)d_in[6];
    const float* w_hh1  = (const float*)d_in[7];
    const float* b_ih1  = (const float*)d_in[8];
    const float* b_hh1  = (const float*)d_in[9];
    const float* w_ih2  = (const float*)d_in[10];
    const float* w_hh2  = (const float*)d_in[11];
    const float* b_ih2  = (const float*)d_in[12];
    const float* b_hh2  = (const float*)d_in[13];
    const float* w_out  = (const float*)d_in[14];
    const float* b_out  = (const float*)d_in[15];
    float* out = (float*)d_out;

    lstm_fused_kernel<<<BB, 32>>>(x_main, x_sfc,
                                  w_sfc1, b_sfc1, w_sfc2, b_sfc2,
                                  w_ih1, w_hh1, b_ih1, b_hh1,
                                  w_ih2, w_hh2, b_ih2, b_hh2,
                                  w_out, b_out, out);
}

// round 9
// speedup vs baseline: 1.6667x; 1.0266x over previous
#include <cuda_runtime.h>

#define BB 8192
#define SS 64

typedef unsigned long long ull;

// L2 input-projection scratch: [B][S][128] scalar gate pre-activations (bias included). 128 MB.
__device__ float g_xg2[(size_t)BB * SS * 128];

__device__ __forceinline__ ull ffma2(ull a, ull b, ull c) {
    ull d;
    asm("fma.rn.f32x2 %0, %1, %2, %3;" : "=l"(d) : "l"(a), "l"(b), "l"(c));
    return d;
}
__device__ __forceinline__ ull add2(ull a, ull b) {
    ull d;
    asm("add.rn.f32x2 %0, %1, %2;" : "=l"(d) : "l"(a), "l"(b));
    return d;
}
__device__ __forceinline__ ull pack2(float lo, float hi) {
    ull d;
    asm("mov.b64 %0, {%1, %2};" : "=l"(d) : "f"(lo), "f"(hi));
    return d;
}
__device__ __forceinline__ void unpack2(ull v, float& lo, float& hi) {
    asm("mov.b64 {%0, %1}, %2;" : "=f"(lo), "=f"(hi) : "l"(v));
}
__device__ __forceinline__ float sigf(float x)   { return 1.0f / (1.0f + __expf(-x)); }
__device__ __forceinline__ float tanhf_(float x) { return 1.0f - 2.0f / (__expf(2.0f * x) + 1.0f); }

// Load 4 gate rows (r = g*32+u) of a [128][32] matrix as adjacent-pair packed ulls.
// wh[g][k] = (W[r][2k], W[r][2k+1]) — straight reinterpret, no packing math.
__device__ __forceinline__ void load_rows(const float* __restrict__ W, int u, ull wh[4][16]) {
#pragma unroll
    for (int g = 0; g < 4; g++) {
        const ulonglong2* wr = reinterpret_cast<const ulonglong2*>(W + (g * 32 + u) * 32);
#pragma unroll
        for (int q = 0; q < 8; q++) {
            ulonglong2 v = wr[q];
            wh[g][2 * q]     = v.x;
            wh[g][2 * q + 1] = v.y;
        }
    }
}

// Dual-partial dot over a 32-float smem row: accA/accB are 4 gates x (even,odd) partial pairs.
__device__ __forceinline__ void dot32(const float* __restrict__ row,
                                      const ull wh[4][16], ull accA[4], ull accB[4]) {
    const ulonglong2* hp = reinterpret_cast<const ulonglong2*>(row);
#pragma unroll
    for (int q = 0; q < 8; q++) {
        ulonglong2 hd = hp[q];              // LDS.128 broadcast: (h0,h1),(h2,h3) pairs
#pragma unroll
        for (int g = 0; g < 4; g++) {
            accA[g] = ffma2(wh[g][2 * q],     hd.x, accA[g]);
            accB[g] = ffma2(wh[g][2 * q + 1], hd.y, accB[g]);
        }
    }
}

__device__ __forceinline__ float hsum(ull a, ull b) {
    float lo, hi;
    unpack2(add2(a, b), lo, hi);
    return lo + hi;
}

__device__ __forceinline__ void lstm_update(const float pre[4], float& h, float& c) {
    const float ig = sigf(pre[0]);
    const float fg = sigf(pre[1]);
    const float gg = tanhf_(pre[2]);
    const float og = sigf(pre[3]);
    c = fg * c + ig * gg;
    h = og * tanhf_(c);
}

__global__ void __launch_bounds__(32, 10)
lstm_fused_kernel(const float* __restrict__ x_main,   // [B,S,4]
                  const float* __restrict__ x_sfc,    // [B,5]
                  const float* __restrict__ w_sfc1, const float* __restrict__ b_sfc1,
                  const float* __restrict__ w_sfc2, const float* __restrict__ b_sfc2,
                  const float* __restrict__ w_ih1,  const float* __restrict__ w_hh1,
                  const float* __restrict__ b_ih1,  const float* __restrict__ b_hh1,
                  const float* __restrict__ w_ih2,  const float* __restrict__ w_hh2,
                  const float* __restrict__ b_ih2,  const float* __restrict__ b_hh2,
                  const float* __restrict__ w_out,  const float* __restrict__ b_out,
                  float* __restrict__ out)            // [B,S,1]
{
    // Rows 0..63: L1 output history. Row 64: h0 / L2 state buf A. Row 65: L2 state buf B.
    __shared__ __align__(16) float hist[(SS + 2) * 32];

    const int u = threadIdx.x;      // hidden unit (lane)
    const int b = blockIdx.x;       // batch element (1 warp per block)

    // ---------------- h0, c0 from surface MLPs ----------------
    float h, c;
    {
        float sf[5];
#pragma unroll
        for (int k = 0; k < 5; k++) sf[k] = x_sfc[b * 5 + k];
        float a1 = b_sfc1[u];
        float a2 = b_sfc2[u];
#pragma unroll
        for (int k = 0; k < 5; k++) {
            a1 += w_sfc1[u * 5 + k] * sf[k];
            a2 += w_sfc2[u * 5 + k] * sf[k];
        }
        h = tanhf_(a1);
        c = tanhf_(a2);
    }

    // ---------------- Phase 1: Layer-1 recurrence over time-reversed input ----------------
    {
        ull wh[4][16];
        load_rows(w_hh1, u, wh);
        ull wx[4][2];
        ull bseed[4];
#pragma unroll
        for (int g = 0; g < 4; g++) {
            const int r = g * 32 + u;
            ulonglong2 v = reinterpret_cast<const ulonglong2*>(w_ih1)[r]; // row = 4 floats = 16B
            wx[g][0] = v.x;                 // (w[0], w[1])
            wx[g][1] = v.y;                 // (w[2], w[3])
            bseed[g] = pack2(b_ih1[r] + b_hh1[r], 0.0f);
        }

        hist[SS * 32 + u] = h;              // h_prev for first step lives in row 64
        __syncthreads();

        const float4* xb = reinterpret_cast<const float4*>(x_main + (size_t)b * SS * 4);
        float4 xv = xb[SS - 1];             // prefetch first (reversed) input

        for (int t = 0; t < SS; t++) {
            const int s = SS - 1 - t;       // reversed-time input; output slot s (flip back)
            float4 xv_next = (s > 0) ? xb[s - 1] : xv;

            const ull xd01 = pack2(xv.x, xv.y);
            const ull xd23 = pack2(xv.z, xv.w);

            ull accA[4], accB[4];
#pragma unroll
            for (int g = 0; g < 4; g++) {
                accA[g] = ffma2(wx[g][0], xd01, bseed[g]);
                accB[g] = ffma2(wx[g][1], xd23, 0ULL);
            }
            dot32(hist + (s + 1) * 32, wh, accA, accB);

            float pre[4];
#pragma unroll
            for (int g = 0; g < 4; g++) pre[g] = hsum(accA[g], accB[g]);
            lstm_update(pre, h, c);

            hist[s * 32 + u] = h;
            __syncthreads();                // nw=1 BAR (~3 cyc); orders cross-lane STS->LDS
            xv = xv_next;
        }
    }

    // ---------------- Phase 2: L2 input projection (time-parallel) -> scratch ----------------
    {
        ull wh[4][16];
        load_rows(w_ih2, u, wh);
        ull bseed[4];
#pragma unroll
        for (int g = 0; g < 4; g++) {
            const int r = g * 32 + u;
            bseed[g] = pack2(b_ih2[r] + b_hh2[r], 0.0f);
        }
        float* __restrict__ dst = g_xg2 + (size_t)b * SS * 128;

        for (int t = 0; t < SS; t++) {
            ull accA[4], accB[4];
#pragma unroll
            for (int g = 0; g < 4; g++) { accA[g] = bseed[g]; accB[g] = 0ULL; }
            dot32(hist + t * 32, wh, accA, accB);
#pragma unroll
            for (int g = 0; g < 4; g++)
                dst[t * 128 + g * 32 + u] = hsum(accA[g], accB[g]);  // coalesced STG.32
        }
    }

    // ---------------- Phase 3: L2 recurrence + output projection ----------------
    {
        ull wh[4][16];
        load_rows(w_hh2, u, wh);
        const float wo = w_out[u];
        const float bo = b_out[0];
        const float* __restrict__ src = g_xg2 + (size_t)b * SS * 128;

        float h2 = 0.0f, c2 = 0.0f;
        hist[SS * 32 + u] = 0.0f;           // state buffer A (row 64) <- zeros

        // 2-deep prefetch of gate pre-activations
        float p0[4], p1[4];
#pragma unroll
        for (int g = 0; g < 4; g++) {
            p0[g] = src[g * 32 + u];
            p1[g] = src[128 + g * 32 + u];
        }
        __syncthreads();

        for (int t = 0; t < SS; t++) {
            ull accA[4], accB[4];
#pragma unroll
            for (int g = 0; g < 4; g++) {
                accA[g] = pack2(p0[g], 0.0f);   // bias already folded in scratch
                accB[g] = 0ULL;
                p0[g] = p1[g];
            }
            if (t + 2 < SS) {
#pragma unroll
                for (int g = 0; g < 4; g++) p1[g] = src[(t + 2) * 128 + g * 32 + u];
            }

            const int rd = SS + (t & 1);        // double-buffered state rows 64/65
            const int wr = SS + ((t & 1) ^ 1);
            dot32(hist + rd * 32, wh, accA, accB);

            float pre[4];
#pragma unroll
            for (int g = 0; g < 4; g++) pre[g] = hsum(accA[g], accB[g]);
            lstm_update(pre, h2, c2);

            hist[wr * 32 + u] = h2;

            // y[b,t] = w_out . h2 + b_out (NY=1): butterfly reduction
            float p = wo * h2;
#pragma unroll
            for (int off = 16; off; off >>= 1)
                p += __shfl_xor_sync(0xffffffffu, p, off);
            if (u == 0) out[(size_t)b * SS + t] = p + bo;

            __syncthreads();
        }
    }
}

extern "C" void kernel_launch(void* const* d_in, const int* in_sizes, int n_in,
                              void* d_out, int out_size)
{
    const float* x_main = (const float*)d_in[0];
    const float* x_sfc  = (const float*)d_in[1];
    const float* w_sfc1 = (const float*)d_in[2];
    const float* b_sfc1 = (const float*)d_in[3];
    const float* w_sfc2 = (const float*)d_in[4];
    const float* b_sfc2 = (const float*)d_in[5];
    const float* w_ih1  = (const float*)d_in[6];
    const float* w_hh1  = (const float*)d_in[7];
    const float* b_ih1  = (const float*)d_in[8];
    const float* b_hh1  = (const float*)d_in[9];
    const float* w_ih2  = (const float*)d_in[10];
    const float* w_hh2  = (const float*)d_in[11];
    const float* b_ih2  = (const float*)d_in[12];
    const float* b_hh2  = (const float*)d_in[13];
    const float* w_out  = (const float*)d_in[14];
    const float* b_out  = (const float*)d_in[15];
    float* out = (float*)d_out;

    lstm_fused_kernel<<<BB, 32>>>(x_main, x_sfc,
                                  w_sfc1, b_sfc1, w_sfc2, b_sfc2,
                                  w_ih1, w_hh1, b_ih1, b_hh1,
                                  w_ih2, w_hh2, b_ih2, b_hh2,
                                  w_out, b_out, out);
}